// round 2
// baseline (speedup 1.0000x reference)
#include <cuda_runtime.h>
#include <cstdint>

#define NN 100000      // nodes
#define NE 3200000     // edges
#define NF 512
#define NH 256
#define NC 40

// ---------------- scratch (static device globals; no allocation) ----------------
__device__ float g_deg [NN];
__device__ float g_dinv[NN];
__device__ float g_norm[NE];
__device__ float g_h1  [(size_t)NN * NH];   // 102.4 MB
__device__ float g_agg1[(size_t)NN * NH];   // 102.4 MB
__device__ float g_h2  [(size_t)NN * NC];   // 16 MB
__device__ float g_agg2[(size_t)NN * NC];   // 16 MB

// vector reduction: 16B atomic add (PTX ISA 8.1+, sm_90+)
__device__ __forceinline__ void red4(float4* p, float4 v) {
    asm volatile("red.global.add.v4.f32 [%0], {%1, %2, %3, %4};"
                 :: "l"(p), "f"(v.x), "f"(v.y), "f"(v.z), "f"(v.w) : "memory");
}

// ---------------- degree / norm ----------------
__global__ void k_deg_init(int n) {
    int i = blockIdx.x * blockDim.x + threadIdx.x;
    if (i < n) g_deg[i] = 1.0f;            // self loop
}

__global__ void k_deg_edges(const int* __restrict__ ei, int E) {
    int i = blockIdx.x * blockDim.x + threadIdx.x;
    if (i < E) {
        int d = ei[E + i];
        if ((unsigned)d < (unsigned)NN) atomicAdd(&g_deg[d], 1.0f);
    }
}

__global__ void k_dinv(int n) {
    int i = blockIdx.x * blockDim.x + threadIdx.x;
    if (i < n) g_dinv[i] = rsqrtf(g_deg[i]);
}

__global__ void k_norm(const int* __restrict__ ei, int E) {
    int i = blockIdx.x * blockDim.x + threadIdx.x;
    if (i < E) {
        int s = ei[i];
        int d = ei[E + i];
        g_norm[i] = g_dinv[s] * g_dinv[d];
    }
}

// ---------------- GEMM1: h1 = x @ W1 ; agg1 = h1 * dinv^2 (self loop) ----------------
// A: [M,512], B(W1): [512,256]. BM=128 BN=64 BK=16, 128 threads, 8x8 per thread.
__global__ __launch_bounds__(128) void k_gemm1(const float* __restrict__ A,
                                               const float* __restrict__ B, int M) {
    __shared__ float As[16][132];   // transposed, padded
    __shared__ float Bs[16][64];
    const int tid = threadIdx.x;
    const int tx = tid & 7;          // N dir (8 x 8 cols)
    const int ty = tid >> 3;         // M dir (16 x 8 rows)
    const int rowBase = blockIdx.y * 128;
    const int colBase = blockIdx.x * 64;

    float acc[8][8] = {};

    for (int k0 = 0; k0 < NF; k0 += 16) {
        #pragma unroll
        for (int i = 0; i < 4; i++) {                 // A tile: 512 float4
            int f4 = tid + i * 128;
            int m = f4 >> 2, k4 = f4 & 3;
            int r = rowBase + m; if (r >= M) r = M - 1;
            float4 v = *(const float4*)(A + (size_t)r * NF + k0 + k4 * 4);
            As[k4 * 4 + 0][m] = v.x;
            As[k4 * 4 + 1][m] = v.y;
            As[k4 * 4 + 2][m] = v.z;
            As[k4 * 4 + 3][m] = v.w;
        }
        #pragma unroll
        for (int i = 0; i < 2; i++) {                 // B tile: 256 float4
            int f4 = tid + i * 128;
            int k = f4 >> 4, n4 = f4 & 15;
            *(float4*)&Bs[k][n4 * 4] =
                *(const float4*)(B + (size_t)(k0 + k) * NH + colBase + n4 * 4);
        }
        __syncthreads();
        #pragma unroll
        for (int k = 0; k < 16; k++) {
            float a[8], b[8];
            *(float4*)&a[0] = *(float4*)&As[k][ty * 8];
            *(float4*)&a[4] = *(float4*)&As[k][ty * 8 + 4];
            *(float4*)&b[0] = *(float4*)&Bs[k][tx * 8];
            *(float4*)&b[4] = *(float4*)&Bs[k][tx * 8 + 4];
            #pragma unroll
            for (int i = 0; i < 8; i++)
                #pragma unroll
                for (int j = 0; j < 8; j++)
                    acc[i][j] = fmaf(a[i], b[j], acc[i][j]);
        }
        __syncthreads();
    }

    #pragma unroll
    for (int i = 0; i < 8; i++) {
        int row = rowBase + ty * 8 + i;
        if (row < M) {
            float di = g_dinv[row];
            float di2 = di * di;
            float* hp = g_h1   + (size_t)row * NH + colBase + tx * 8;
            float* ap = g_agg1 + (size_t)row * NH + colBase + tx * 8;
            float4 v0 = make_float4(acc[i][0], acc[i][1], acc[i][2], acc[i][3]);
            float4 v1 = make_float4(acc[i][4], acc[i][5], acc[i][6], acc[i][7]);
            *(float4*)hp       = v0;
            *(float4*)(hp + 4) = v1;
            *(float4*)ap       = make_float4(v0.x * di2, v0.y * di2, v0.z * di2, v0.w * di2);
            *(float4*)(ap + 4) = make_float4(v1.x * di2, v1.y * di2, v1.z * di2, v1.w * di2);
        }
    }
}

// ---------------- scatter1: agg1[dst] += h1[src] * norm  (256 floats/edge, 1 warp/edge) ----------------
__global__ __launch_bounds__(256) void k_scatter1(const int* __restrict__ ei, int E) {
    int gw = (int)((blockIdx.x * 256u + threadIdx.x) >> 5);
    int lane = threadIdx.x & 31;
    if (gw >= E) return;
    int s = ei[gw];
    int d = ei[E + gw];
    float nm = g_norm[gw];
    const float4* hp = (const float4*)(g_h1 + (size_t)s * NH);
    float4* ap = (float4*)(g_agg1 + (size_t)d * NH);
    float4 v0 = hp[lane];
    float4 v1 = hp[lane + 32];
    red4(ap + lane,      make_float4(v0.x * nm, v0.y * nm, v0.z * nm, v0.w * nm));
    red4(ap + lane + 32, make_float4(v1.x * nm, v1.y * nm, v1.z * nm, v1.w * nm));
}

// ---------------- GEMM2: h2 = relu(agg1 + b1) @ W2 ; agg2 = h2 * dinv^2 ----------------
// 64 rows/block, 128 threads, each thread: 2 rows x 10 cols. W2 (40KB) + rows staged in dyn smem.
#define G2_SMEM ((10240 + 64 * 260) * 4)
__global__ __launch_bounds__(128) void k_gemm2(const float* __restrict__ b1,
                                               const float* __restrict__ W2, int M) {
    extern __shared__ float sm[];
    float* W2s = sm;              // 10240 floats
    float* rs  = sm + 10240;      // 64 rows x 260 stride
    const int tid = threadIdx.x;
    const int row0 = blockIdx.x * 64;

    #pragma unroll
    for (int i = 0; i < 20; i++) {                 // W2: 2560 float4
        int f4 = tid + i * 128;
        *(float4*)&W2s[f4 * 4] = *(const float4*)(W2 + (size_t)f4 * 4);
    }
    #pragma unroll
    for (int i = 0; i < 32; i++) {                 // rows: 4096 float4 with relu(x+b1)
        int f4 = tid + i * 128;
        int r = f4 >> 6, kc = f4 & 63;
        int row = row0 + r; if (row >= M) row = M - 1;
        float4 v  = *(const float4*)(g_agg1 + (size_t)row * NH + kc * 4);
        float4 bb = *(const float4*)(b1 + kc * 4);
        v.x = fmaxf(v.x + bb.x, 0.f);
        v.y = fmaxf(v.y + bb.y, 0.f);
        v.z = fmaxf(v.z + bb.z, 0.f);
        v.w = fmaxf(v.w + bb.w, 0.f);
        *(float4*)&rs[r * 260 + kc * 4] = v;
    }
    __syncthreads();

    const int r  = tid >> 2;             // 0..31 -> rows 2r, 2r+1
    const int cb = (tid & 3) * 10;       // col group
    float acc0[10] = {}, acc1[10] = {};
    const float* r0p = &rs[(2 * r    ) * 260];
    const float* r1p = &rs[(2 * r + 1) * 260];
    #pragma unroll 4
    for (int k = 0; k < NH; k++) {
        float a0 = r0p[k], a1 = r1p[k];
        #pragma unroll
        for (int j = 0; j < 10; j++) {
            float w = W2s[k * 40 + cb + j];
            acc0[j] = fmaf(a0, w, acc0[j]);
            acc1[j] = fmaf(a1, w, acc1[j]);
        }
    }
    #pragma unroll
    for (int t = 0; t < 2; t++) {
        int row = row0 + 2 * r + t;
        if (row < M) {
            float di = g_dinv[row], di2 = di * di;
            const float* acc = t ? acc1 : acc0;
            float* hp = g_h2   + (size_t)row * NC + cb;
            float* ap = g_agg2 + (size_t)row * NC + cb;
            #pragma unroll
            for (int j = 0; j < 10; j++) {
                hp[j] = acc[j];
                ap[j] = acc[j] * di2;
            }
        }
    }
}

// ---------------- scatter2: agg2[dst] += h2[src] * norm  (40 floats/edge, 10 float4 chunks) ----------------
__global__ __launch_bounds__(256) void k_scatter2(const int* __restrict__ ei, int E) {
    int idx = blockIdx.x * 256 + threadIdx.x;
    int e = idx / 10;
    if (e >= E) return;
    int c = idx - e * 10;
    int s = ei[e];
    int d = ei[E + e];
    float nm = g_norm[e];
    float4 v = *(const float4*)(g_h2 + (size_t)s * NC + c * 4);
    red4((float4*)(g_agg2 + (size_t)d * NC + c * 4),
         make_float4(v.x * nm, v.y * nm, v.z * nm, v.w * nm));
}

// ---------------- log_softmax(agg2 + b2), 1 warp per row ----------------
__global__ __launch_bounds__(256) void k_lsm(const float* __restrict__ b2,
                                             float* __restrict__ out, int M) {
    int w = (int)((blockIdx.x * 256u + threadIdx.x) >> 5);
    int lane = threadIdx.x & 31;
    if (w >= M) return;
    const float* z = g_agg2 + (size_t)w * NC;
    float x0 = z[lane] + b2[lane];
    float x1 = (lane < 8) ? (z[32 + lane] + b2[32 + lane]) : -3.0e38f;
    float m = fmaxf(x0, x1);
    #pragma unroll
    for (int off = 16; off > 0; off >>= 1)
        m = fmaxf(m, __shfl_xor_sync(0xFFFFFFFFu, m, off));
    float s = __expf(x0 - m) + ((lane < 8) ? __expf(x1 - m) : 0.f);
    #pragma unroll
    for (int off = 16; off > 0; off >>= 1)
        s += __shfl_xor_sync(0xFFFFFFFFu, s, off);
    float l = m + __logf(s);
    out[(size_t)w * NC + lane] = x0 - l;
    if (lane < 8) out[(size_t)w * NC + 32 + lane] = x1 - l;
}

// ---------------- launch ----------------
extern "C" void kernel_launch(void* const* d_in, const int* in_sizes, int n_in,
                              void* d_out, int out_size) {
    const float* x  = (const float*)d_in[0];
    const int*   ei = (const int*)d_in[1];      // JAX default config: int64 -> int32
    const float* W1 = (const float*)d_in[2];
    const float* b1 = (const float*)d_in[3];
    const float* W2 = (const float*)d_in[4];
    const float* b2 = (const float*)d_in[5];
    float* out = (float*)d_out;

    int n = in_sizes[0] / NF;       // 100000
    int E = in_sizes[1] / 2;        // 3200000
    if (n > NN) n = NN;
    if (E > NE) E = NE;

    cudaFuncSetAttribute(k_gemm2, cudaFuncAttributeMaxDynamicSharedMemorySize, G2_SMEM);

    k_deg_init <<<(n + 255) / 256, 256>>>(n);
    k_deg_edges<<<(E + 255) / 256, 256>>>(ei, E);
    k_dinv     <<<(n + 255) / 256, 256>>>(n);
    k_norm     <<<(E + 255) / 256, 256>>>(ei, E);

    {
        dim3 grid(NH / 64, (n + 127) / 128);
        k_gemm1<<<grid, 128>>>(x, W1, n);
    }
    {
        long long tw = (long long)E * 32;
        k_scatter1<<<(unsigned)((tw + 255) / 256), 256>>>(ei, E);
    }
    k_gemm2<<<(n + 63) / 64, 128, G2_SMEM>>>(b1, W2, n);
    {
        long long tw = (long long)E * 10;
        k_scatter2<<<(unsigned)((tw + 255) / 256), 256>>>(ei, E);
    }
    k_lsm<<<((n + 7) / 8), 256>>>(b2, out, n);
}

// round 4
// speedup vs baseline: 1.3720x; 1.3720x over previous
#include <cuda_runtime.h>
#include <cstdint>

#define NN 100000      // nodes
#define NE 3200000     // edges
#define NF 512
#define NH 256
#define NC 40

// ---------------- scratch (static device globals; no allocation) ----------------
__device__ int   g_cnt    [NN];        // in-degree histogram
__device__ int   g_cursor [NN];        // fill cursors
__device__ int   g_rowstart[NN + 1];   // CSR row offsets (by dst)
__device__ float g_dinv   [NN];
__device__ int2  g_edge   [NE];        // packed (src, bitcast(norm)), CSR order
__device__ float g_h1     [(size_t)NN * NH];   // 102.4 MB : x @ W1
__device__ float g_hrelu  [(size_t)NN * NH];   // 102.4 MB : relu(agg1 + b1)
__device__ float g_h2     [(size_t)NN * NC];   // 16 MB    : hrelu @ W2

// ---------------- CSR build ----------------
__global__ void k_zero() {
    int i = blockIdx.x * blockDim.x + threadIdx.x;
    if (i < NN) { g_cnt[i] = 0; g_cursor[i] = 0; }
}

__global__ void k_hist(const int* __restrict__ ei, int E) {
    int i = blockIdx.x * blockDim.x + threadIdx.x;
    if (i < E) {
        int d = ei[E + i];
        if ((unsigned)d < (unsigned)NN) atomicAdd(&g_cnt[d], 1);
    }
}

// single block, 1024 threads: exclusive scan of g_cnt -> g_rowstart, plus dinv
__global__ __launch_bounds__(1024) void k_scan() {
    __shared__ int ssum[1024];
    const int CH = (NN + 1023) / 1024;   // 98
    int t = threadIdx.x;
    int start = t * CH;
    int end = start + CH; if (end > NN) end = NN;
    int s = 0;
    for (int i = start; i < end; i++) s += g_cnt[i];
    ssum[t] = s;
    __syncthreads();
    for (int off = 1; off < 1024; off <<= 1) {
        int v = ssum[t];
        int add = (t >= off) ? ssum[t - off] : 0;
        __syncthreads();
        ssum[t] = v + add;
        __syncthreads();
    }
    int run = (t == 0) ? 0 : ssum[t - 1];
    for (int i = start; i < end; i++) {
        g_rowstart[i] = run;
        run += g_cnt[i];
        g_dinv[i] = rsqrtf((float)g_cnt[i] + 1.0f);   // +1 self loop
    }
    if (start < NN && end == NN) g_rowstart[NN] = run;
}

__global__ void k_fill(const int* __restrict__ ei, int E) {
    int i = blockIdx.x * blockDim.x + threadIdx.x;
    if (i < E) {
        int s = ei[i];
        int d = ei[E + i];
        if ((unsigned)s < (unsigned)NN && (unsigned)d < (unsigned)NN) {
            int pos = g_rowstart[d] + atomicAdd(&g_cursor[d], 1);
            g_edge[pos] = make_int2(s, __float_as_int(g_dinv[s] * g_dinv[d]));
        }
    }
}

// ---------------- GEMM1: h1 = x @ W1 ----------------
// A: [M,512], B(W1): [512,256]. BM=128 BN=64 BK=16, 128 threads, 8x8 per thread.
__global__ __launch_bounds__(128) void k_gemm1(const float* __restrict__ A,
                                               const float* __restrict__ B, int M) {
    __shared__ float As[16][132];   // transposed, padded
    __shared__ float Bs[16][64];
    const int tid = threadIdx.x;
    const int tx = tid & 7;          // N dir
    const int ty = tid >> 3;         // M dir
    const int rowBase = blockIdx.y * 128;
    const int colBase = blockIdx.x * 64;

    float acc[8][8] = {};

    for (int k0 = 0; k0 < NF; k0 += 16) {
        #pragma unroll
        for (int i = 0; i < 4; i++) {
            int f4 = tid + i * 128;
            int m = f4 >> 2, k4 = f4 & 3;
            int r = rowBase + m; if (r >= M) r = M - 1;
            float4 v = *(const float4*)(A + (size_t)r * NF + k0 + k4 * 4);
            As[k4 * 4 + 0][m] = v.x;
            As[k4 * 4 + 1][m] = v.y;
            As[k4 * 4 + 2][m] = v.z;
            As[k4 * 4 + 3][m] = v.w;
        }
        #pragma unroll
        for (int i = 0; i < 2; i++) {
            int f4 = tid + i * 128;
            int k = f4 >> 4, n4 = f4 & 15;
            *(float4*)&Bs[k][n4 * 4] =
                *(const float4*)(B + (size_t)(k0 + k) * NH + colBase + n4 * 4);
        }
        __syncthreads();
        #pragma unroll
        for (int k = 0; k < 16; k++) {
            float a[8], b[8];
            *(float4*)&a[0] = *(float4*)&As[k][ty * 8];
            *(float4*)&a[4] = *(float4*)&As[k][ty * 8 + 4];
            *(float4*)&b[0] = *(float4*)&Bs[k][tx * 8];
            *(float4*)&b[4] = *(float4*)&Bs[k][tx * 8 + 4];
            #pragma unroll
            for (int i = 0; i < 8; i++)
                #pragma unroll
                for (int j = 0; j < 8; j++)
                    acc[i][j] = fmaf(a[i], b[j], acc[i][j]);
        }
        __syncthreads();
    }

    #pragma unroll
    for (int i = 0; i < 8; i++) {
        int row = rowBase + ty * 8 + i;
        if (row < M) {
            float* hp = g_h1 + (size_t)row * NH + colBase + tx * 8;
            *(float4*)hp       = make_float4(acc[i][0], acc[i][1], acc[i][2], acc[i][3]);
            *(float4*)(hp + 4) = make_float4(acc[i][4], acc[i][5], acc[i][6], acc[i][7]);
        }
    }
}

// ---------------- gather1: hrelu[d] = relu(b1 + h1[d]*dinv^2 + sum h1[s]*norm) ----------------
__global__ __launch_bounds__(256) void k_gather1(const float* __restrict__ b1, int M) {
    int w = (int)((blockIdx.x * 256u + threadIdx.x) >> 5);
    int lane = threadIdx.x & 31;
    if (w >= M) return;
    float di = g_dinv[w];
    float di2 = di * di;
    const float4* hp = (const float4*)(g_h1 + (size_t)w * NH);
    float4 a0 = hp[lane];
    float4 a1 = hp[lane + 32];
    a0.x *= di2; a0.y *= di2; a0.z *= di2; a0.w *= di2;
    a1.x *= di2; a1.y *= di2; a1.z *= di2; a1.w *= di2;

    int beg = g_rowstart[w], end = g_rowstart[w + 1];
    for (int e0 = beg; e0 < end; e0 += 32) {
        int n = end - e0; if (n > 32) n = 32;
        int2 ed = make_int2(0, 0);
        if (e0 + lane < end) ed = g_edge[e0 + lane];
        #pragma unroll 4
        for (int j = 0; j < n; j++) {
            int   s  = __shfl_sync(0xFFFFFFFFu, ed.x, j);
            float nm = __int_as_float(__shfl_sync(0xFFFFFFFFu, ed.y, j));
            const float4* sp = (const float4*)(g_h1 + (size_t)s * NH);
            float4 v0 = sp[lane];
            float4 v1 = sp[lane + 32];
            a0.x = fmaf(v0.x, nm, a0.x); a0.y = fmaf(v0.y, nm, a0.y);
            a0.z = fmaf(v0.z, nm, a0.z); a0.w = fmaf(v0.w, nm, a0.w);
            a1.x = fmaf(v1.x, nm, a1.x); a1.y = fmaf(v1.y, nm, a1.y);
            a1.z = fmaf(v1.z, nm, a1.z); a1.w = fmaf(v1.w, nm, a1.w);
        }
    }
    const float4* bp = (const float4*)b1;
    float4 bb0 = bp[lane], bb1 = bp[lane + 32];
    a0.x = fmaxf(a0.x + bb0.x, 0.f); a0.y = fmaxf(a0.y + bb0.y, 0.f);
    a0.z = fmaxf(a0.z + bb0.z, 0.f); a0.w = fmaxf(a0.w + bb0.w, 0.f);
    a1.x = fmaxf(a1.x + bb1.x, 0.f); a1.y = fmaxf(a1.y + bb1.y, 0.f);
    a1.z = fmaxf(a1.z + bb1.z, 0.f); a1.w = fmaxf(a1.w + bb1.w, 0.f);
    float4* op = (float4*)(g_hrelu + (size_t)w * NH);
    __stcs(op + lane,      a0);   // evict-first: keep h1 resident in L2
    __stcs(op + lane + 32, a1);
}

// ---------------- GEMM2: h2 = hrelu @ W2 (no bias/relu here) ----------------
#define G2_SMEM ((10240 + 64 * 260) * 4)
__global__ __launch_bounds__(128) void k_gemm2(const float* __restrict__ W2, int M) {
    extern __shared__ float sm[];
    float* W2s = sm;              // 10240 floats
    float* rs  = sm + 10240;      // 64 rows x 260 stride
    const int tid = threadIdx.x;
    const int row0 = blockIdx.x * 64;

    #pragma unroll
    for (int i = 0; i < 20; i++) {
        int f4 = tid + i * 128;
        *(float4*)&W2s[f4 * 4] = *(const float4*)(W2 + (size_t)f4 * 4);
    }
    #pragma unroll
    for (int i = 0; i < 32; i++) {
        int f4 = tid + i * 128;
        int r = f4 >> 6, kc = f4 & 63;
        int row = row0 + r; if (row >= M) row = M - 1;
        float4 v = __ldcs((const float4*)(g_hrelu + (size_t)row * NH + kc * 4));
        *(float4*)&rs[r * 260 + kc * 4] = v;
    }
    __syncthreads();

    const int r  = tid >> 2;
    const int cb = (tid & 3) * 10;
    float acc0[10] = {}, acc1[10] = {};
    const float* r0p = &rs[(2 * r    ) * 260];
    const float* r1p = &rs[(2 * r + 1) * 260];
    #pragma unroll 4
    for (int k = 0; k < NH; k++) {
        float a0 = r0p[k], a1 = r1p[k];
        #pragma unroll
        for (int j = 0; j < 10; j++) {
            float w = W2s[k * 40 + cb + j];
            acc0[j] = fmaf(a0, w, acc0[j]);
            acc1[j] = fmaf(a1, w, acc1[j]);
        }
    }
    #pragma unroll
    for (int t = 0; t < 2; t++) {
        int row = row0 + 2 * r + t;
        if (row < M) {
            const float* acc = t ? acc1 : acc0;
            float* hp = g_h2 + (size_t)row * NC + cb;
            #pragma unroll
            for (int j = 0; j < 10; j++) hp[j] = acc[j];
        }
    }
}

// ---------------- gather2 + bias + log_softmax, warp per node ----------------
__global__ __launch_bounds__(256) void k_gather2(const float* __restrict__ b2,
                                                 float* __restrict__ out, int M) {
    int w = (int)((blockIdx.x * 256u + threadIdx.x) >> 5);
    int lane = threadIdx.x & 31;
    if (w >= M) return;
    float di = g_dinv[w];
    float di2 = di * di;
    float4 acc = make_float4(0.f, 0.f, 0.f, 0.f);
    if (lane < 10) {
        float4 v = ((const float4*)(g_h2 + (size_t)w * NC))[lane];
        acc = make_float4(v.x * di2, v.y * di2, v.z * di2, v.w * di2);
    }
    int beg = g_rowstart[w], end = g_rowstart[w + 1];
    for (int e0 = beg; e0 < end; e0 += 32) {
        int n = end - e0; if (n > 32) n = 32;
        int2 ed = make_int2(0, 0);
        if (e0 + lane < end) ed = g_edge[e0 + lane];
        #pragma unroll 4
        for (int j = 0; j < n; j++) {
            int   s  = __shfl_sync(0xFFFFFFFFu, ed.x, j);
            float nm = __int_as_float(__shfl_sync(0xFFFFFFFFu, ed.y, j));
            if (lane < 10) {
                float4 v = ((const float4*)(g_h2 + (size_t)s * NC))[lane];
                acc.x = fmaf(v.x, nm, acc.x);
                acc.y = fmaf(v.y, nm, acc.y);
                acc.z = fmaf(v.z, nm, acc.z);
                acc.w = fmaf(v.w, nm, acc.w);
            }
        }
    }
    // add bias, log_softmax over 40 values held by lanes 0..9
    float m = -3.0e38f;
    if (lane < 10) {
        float4 bb = ((const float4*)b2)[lane];
        acc.x += bb.x; acc.y += bb.y; acc.z += bb.z; acc.w += bb.w;
        m = fmaxf(fmaxf(acc.x, acc.y), fmaxf(acc.z, acc.w));
    }
    #pragma unroll
    for (int off = 16; off > 0; off >>= 1)
        m = fmaxf(m, __shfl_xor_sync(0xFFFFFFFFu, m, off));
    float s = 0.f;
    if (lane < 10)
        s = __expf(acc.x - m) + __expf(acc.y - m) + __expf(acc.z - m) + __expf(acc.w - m);
    #pragma unroll
    for (int off = 16; off > 0; off >>= 1)
        s += __shfl_xor_sync(0xFFFFFFFFu, s, off);
    float l = m + __logf(s);
    if (lane < 10) {
        float4 o = make_float4(acc.x - l, acc.y - l, acc.z - l, acc.w - l);
        ((float4*)(out + (size_t)w * NC))[lane] = o;
    }
}

// ---------------- launch ----------------
extern "C" void kernel_launch(void* const* d_in, const int* in_sizes, int n_in,
                              void* d_out, int out_size) {
    const float* x  = (const float*)d_in[0];
    const int*   ei = (const int*)d_in[1];      // JAX default config: int64 -> int32
    const float* W1 = (const float*)d_in[2];
    const float* b1 = (const float*)d_in[3];
    const float* W2 = (const float*)d_in[4];
    const float* b2 = (const float*)d_in[5];
    float* out = (float*)d_out;

    int n = in_sizes[0] / NF;       // 100000
    int E = in_sizes[1] / 2;        // 3200000
    if (n > NN) n = NN;
    if (E > NE) E = NE;

    cudaFuncSetAttribute(k_gemm2, cudaFuncAttributeMaxDynamicSharedMemorySize, G2_SMEM);

    k_zero<<<(NN + 255) / 256, 256>>>();
    k_hist<<<(E + 255) / 256, 256>>>(ei, E);
    k_scan<<<1, 1024>>>();
    k_fill<<<(E + 255) / 256, 256>>>(ei, E);

    {
        dim3 grid(NH / 64, (n + 127) / 128);
        k_gemm1<<<grid, 128>>>(x, W1, n);
    }
    k_gather1<<<(n + 7) / 8, 256>>>(b1, n);
    k_gemm2<<<(n + 63) / 64, 128, G2_SMEM>>>(W2, n);
    k_gather2<<<(n + 7) / 8, 256>>>(b2, out, n);
}